// round 17
// baseline (speedup 1.0000x reference)
#include <cuda_runtime.h>
#include <math.h>
#include <float.h>

#define B    64
#define P    196
#define ENC  2048
#define H    512
#define E    512
#define A_DIM 512
#define V    30000
#define T    20

#define NS_HC    8   // h0/c0 split-K
#define NS_AG    8   // att_h+gate split-K (chunk 64 over K=512)
#define NS_GATES 12  // gates split-K (chunk 256 over K=3072)
#define GATE_OFF (NS_AG * B * A_DIM)
#define MSAVE    1280
#define GRID     148  // persistent grid: <= SM count, all co-resident

// ---------------- scratch (device globals, no allocations) ----------------
__device__ __align__(128) float g_att_enc[B * P * A_DIM];
__device__ __align__(128) float g_part[NS_GATES * B * 4 * H];
__device__ __align__(128) float g_mean[B * ENC];
__device__ __align__(128) float g_h[B * H];
__device__ __align__(128) float g_c[B * H];
__device__ __align__(128) float g_alpha[B * P];
__device__ __align__(128) float g_inp[B * (E + ENC)];
__device__ __align__(128) float g_hsave[MSAVE * H];

// grid barrier state
__device__ unsigned g_barcnt = 0;
__device__ volatile unsigned g_bargen = 0;

__device__ __forceinline__ float sigm(float x) { return 1.f / (1.f + expf(-x)); }

__device__ __forceinline__ void gridbar()
{
    __syncthreads();
    if (threadIdx.x == 0) {
        __threadfence();
        const unsigned gen = g_bargen;
        if (atomicAdd(&g_barcnt, 1u) == GRID - 1u) {
            g_barcnt = 0u;
            __threadfence();
            g_bargen = gen + 1u;
        } else {
            while (g_bargen == gen) { __nanosleep(64); }
        }
        __threadfence();
    }
    __syncthreads();
}

// ---------------- 64x64 split-K tile job, 256 threads, 4x4 microtile ------
// Per-output accumulation: kk ascending within chunk — bit-identical to the
// previous gemm64 kernels (same chunk boundaries, same partial layout).
__device__ __forceinline__ void tile64(float* pool,
    const float* __restrict__ Ab, int ldA,
    const float* __restrict__ Wb, int ldW,
    float* __restrict__ Cb, int ldc, bool sig, int kchunk)
{
    float* As = pool;           // [16][64]
    float* Ws = pool + 1024;    // [16][64]
    const int t  = threadIdx.x;
    const int lr = t & 63;
    const int lkq = (t >> 6) << 2;       // 0,4,8,12
    const float* Ap = Ab + (size_t)lr * ldA + lkq;
    const float* Wp = Wb + (size_t)lr * ldW + lkq;
    const int tx = t & 15, ty = t >> 4;

    float acc[4][4];
#pragma unroll
    for (int i = 0; i < 4; i++)
#pragma unroll
        for (int j = 0; j < 4; j++) acc[i][j] = 0.f;

    float4 a = *(const float4*)Ap;
    float4 w = *(const float4*)Wp;
    for (int kk0 = 0; kk0 < kchunk; kk0 += 16) {
        float4 sa = a;
        if (sig) { sa.x = sigm(sa.x); sa.y = sigm(sa.y); sa.z = sigm(sa.z); sa.w = sigm(sa.w); }
        __syncthreads();
        As[(lkq + 0) * 64 + lr] = sa.x; As[(lkq + 1) * 64 + lr] = sa.y;
        As[(lkq + 2) * 64 + lr] = sa.z; As[(lkq + 3) * 64 + lr] = sa.w;
        Ws[(lkq + 0) * 64 + lr] = w.x;  Ws[(lkq + 1) * 64 + lr] = w.y;
        Ws[(lkq + 2) * 64 + lr] = w.z;  Ws[(lkq + 3) * 64 + lr] = w.w;
        __syncthreads();
        if (kk0 + 16 < kchunk) {
            a = *(const float4*)(Ap + kk0 + 16);
            w = *(const float4*)(Wp + kk0 + 16);
        }
#pragma unroll
        for (int kk = 0; kk < 16; kk++) {
            const float4 ra = *(const float4*)&As[kk * 64 + ty * 4];
            const float4 rw = *(const float4*)&Ws[kk * 64 + tx * 4];
            acc[0][0] += ra.x * rw.x; acc[0][1] += ra.x * rw.y; acc[0][2] += ra.x * rw.z; acc[0][3] += ra.x * rw.w;
            acc[1][0] += ra.y * rw.x; acc[1][1] += ra.y * rw.y; acc[1][2] += ra.y * rw.z; acc[1][3] += ra.y * rw.w;
            acc[2][0] += ra.z * rw.x; acc[2][1] += ra.z * rw.y; acc[2][2] += ra.z * rw.z; acc[2][3] += ra.z * rw.w;
            acc[3][0] += ra.w * rw.x; acc[3][1] += ra.w * rw.y; acc[3][2] += ra.w * rw.z; acc[3][3] += ra.w * rw.w;
        }
    }
#pragma unroll
    for (int i = 0; i < 4; i++)
        *(float4*)(Cb + (size_t)(ty * 4 + i) * ldc + tx * 4) =
            make_float4(acc[i][0], acc[i][1], acc[i][2], acc[i][3]);
}

// ---------------- per-b scores + softmax job ----------------
__device__ __forceinline__ void scores_job(float* pool, int b,
    const float* __restrict__ bh, const float* __restrict__ Wa, const float* __restrict__ ba)
{
    float* sh_h = pool;
    float* sh_w = pool + 512;
    float* sc   = pool + 1024;
    float* red  = pool + 1280;
    const int tid = threadIdx.x;
    __syncthreads();
    for (int a = tid; a < A_DIM; a += 256) {
        float s = bh[a];
#pragma unroll
        for (int ss = 0; ss < NS_AG; ss++) s += g_part[(size_t)(ss * 64 + b) * A_DIM + a];
        sh_h[a] = s;
        sh_w[a] = Wa[a];
    }
    __syncthreads();
    const int w = tid >> 5, lane = tid & 31;
    for (int p = w; p < P; p += 8) {
        const float* row = g_att_enc + (size_t)(b * P + p) * A_DIM;
        float s = 0.f;
#pragma unroll 4
        for (int a = lane; a < A_DIM; a += 32) {
            const float v = row[a] + sh_h[a];
            s += fmaxf(v, 0.f) * sh_w[a];
        }
#pragma unroll
        for (int off = 16; off; off >>= 1) s += __shfl_xor_sync(0xffffffff, s, off);
        if (lane == 0) sc[p] = s + ba[0];
    }
    __syncthreads();
    const float v = (tid < P) ? sc[tid] : -FLT_MAX;
    red[tid] = v;
    __syncthreads();
    for (int off = 128; off; off >>= 1) { if (tid < off) red[tid] = fmaxf(red[tid], red[tid + off]); __syncthreads(); }
    const float mx = red[0];
    __syncthreads();
    const float e = (tid < P) ? expf(v - mx) : 0.f;
    red[tid] = e;
    __syncthreads();
    for (int off = 128; off; off >>= 1) { if (tid < off) red[tid] += red[tid + off]; __syncthreads(); }
    const float inv = 1.f / red[0];
    if (tid < P) g_alpha[b * P + tid] = e * inv;
}

// ---------------- persistent recurrent-loop kernel ----------------
__global__ void __launch_bounds__(256) loop_k(
    const float* __restrict__ enc, const int* __restrict__ cap,
    const float* __restrict__ emb,
    const float* __restrict__ W_ih, const float* __restrict__ b_ih,
    const float* __restrict__ W_hh, const float* __restrict__ b_hh,
    const float* __restrict__ Wh,   const float* __restrict__ bh,
    const float* __restrict__ Wa,   const float* __restrict__ ba,
    const float* __restrict__ Wg,   const float* __restrict__ bg)
{
    __shared__ float pool[2048];
    const int tid = threadIdx.x;

    for (int t = 0; t < T - 1; t++) {
        // ---- Phase A: att_h (h@Wh^T) + gate (sigmoid(h)@Wg^T) partials ----
        for (int j = blockIdx.x; j < 40 * NS_AG; j += GRID) {
            const int s = j / 40;
            const int x = j - s * 40;
            const int k0b = s * (H / NS_AG);
            if (x < 8) {
                tile64(pool, g_h + k0b, H, Wh + (size_t)(x * 64) * H + k0b, H,
                       g_part + (size_t)s * 64 * A_DIM + x * 64, A_DIM, false, H / NS_AG);
            } else {
                const int xg = x - 8;
                tile64(pool, g_h + k0b, H, Wg + (size_t)(xg * 64) * H + k0b, H,
                       g_part + GATE_OFF + (size_t)s * 64 * ENC + xg * 64, ENC, true, H / NS_AG);
            }
        }
        gridbar();

        // ---- Phase B: att_h reduce + scores + softmax ----
        for (int b = blockIdx.x; b < B; b += GRID)
            scores_job(pool, b, bh, Wa, ba);
        gridbar();

        // ---- Phase C: weighted + gate-reduce + inp build + emb gather ----
        for (int j = blockIdx.x; j < (B * (E + ENC)) / 256; j += GRID) {
            float* sa = pool;
            const int idx = j * 256 + tid;
            const int b = idx / (E + ENC);
            const int jj = idx - b * (E + ENC);
            __syncthreads();
            if (tid < P) sa[tid] = g_alpha[b * P + tid];
            __syncthreads();
            if (jj < E) {
                const int tok = cap[b * T + t];
                g_inp[idx] = emb[(size_t)tok * E + jj];
            } else {
                const int ee = jj - E;
                const float* col = enc + (size_t)b * P * ENC + ee;
                float s = 0.f;
#pragma unroll 8
                for (int p = 0; p < P; p++) s += sa[p] * col[(size_t)p * ENC];
                float g = bg[ee];
#pragma unroll
                for (int ss = 0; ss < NS_AG; ss++) g += g_part[GATE_OFF + (size_t)(ss * 64 + b) * ENC + ee];
                g_inp[idx] = s * g;
            }
        }
        gridbar();

        // ---- Phase D: gates partials (dual-region K=3072) ----
        for (int j = blockIdx.x; j < 32 * NS_GATES; j += GRID) {
            const int s = j >> 5;
            const int x = j & 31;
            const int n0 = x * 64;
            const int k0b = s * 256;
            if (k0b >= E + ENC) {
                const int kr = k0b - (E + ENC);
                tile64(pool, g_h + kr, H, W_hh + (size_t)n0 * H + kr, H,
                       g_part + (size_t)s * 64 * (4 * H) + n0, 4 * H, false, 256);
            } else {
                tile64(pool, g_inp + k0b, E + ENC, W_ih + (size_t)n0 * (E + ENC) + k0b, E + ENC,
                       g_part + (size_t)s * 64 * (4 * H) + n0, 4 * H, false, 256);
            }
        }
        gridbar();

        // ---- Phase E: LSTM cell ----
        for (int j = blockIdx.x; j < (B * H) / 256; j += GRID) {
            const int idx = j * 256 + tid;
            const int b = idx >> 9;
            const int n = idx & (H - 1);
            float gv[4];
#pragma unroll
            for (int q = 0; q < 4; q++) {
                const int pos = q * H + n;
                float s = b_ih[pos] + b_hh[pos];
#pragma unroll
                for (int ss = 0; ss < NS_GATES; ss++) s += g_part[(size_t)(ss * 64 + b) * (4 * H) + pos];
                gv[q] = s;
            }
            const float i_ = sigm(gv[0]);
            const float f_ = sigm(gv[1]);
            const float gg = tanhf(gv[2]);
            const float o_ = sigm(gv[3]);
            const float c  = f_ * g_c[idx] + i_ * gg;
            g_c[idx] = c;
            const float hv = o_ * tanhf(c);
            g_h[idx] = hv;
            g_hsave[(size_t)t * (B * H) + idx] = hv;
        }
        gridbar();
    }
}

// =====================================================================
// gemm64 (MODE 4 only): dual h0/c0 split-K, 128 thr, 8x4 microtile.
// =====================================================================
__global__ void __launch_bounds__(128) gemm64_hc_k(
    const float* __restrict__ A1,
    const float* __restrict__ W1,
    const float* __restrict__ W2,
    float* __restrict__ C, int kchunk)
{
    __shared__ float As[16][64];
    __shared__ float Ws[16][64];
    const int tid = threadIdx.x;
    const int s   = blockIdx.y;
    const int k0b = s * kchunk;
    const bool isc = blockIdx.x >= (H / 64);
    const float* Abase = A1 + k0b;
    const float* Wbase = (isc ? W2 : W1) + k0b;
    float* Cb = C + (size_t)s * 64 * (2 * H) + (isc ? H : 0);
    const int n0 = (isc ? (blockIdx.x - H / 64) : blockIdx.x) * 64;

    const int lr = tid & 63;
    const int lk = (tid >> 6) * 8;
    const float* Ap = Abase + (size_t)lr * ENC + lk;
    const float* Wp = Wbase + (size_t)(n0 + lr) * ENC + lk;
    const int tx = tid & 15;
    const int ty = tid >> 4;

    float acc[8][4];
#pragma unroll
    for (int i = 0; i < 8; i++)
#pragma unroll
        for (int j = 0; j < 4; j++) acc[i][j] = 0.f;

    float4 a0 = *(const float4*)(Ap);
    float4 a1 = *(const float4*)(Ap + 4);
    float4 w0 = *(const float4*)(Wp);
    float4 w1 = *(const float4*)(Wp + 4);

    for (int kk0 = 0; kk0 < kchunk; kk0 += 16) {
        __syncthreads();
        As[lk + 0][lr] = a0.x; As[lk + 1][lr] = a0.y; As[lk + 2][lr] = a0.z; As[lk + 3][lr] = a0.w;
        As[lk + 4][lr] = a1.x; As[lk + 5][lr] = a1.y; As[lk + 6][lr] = a1.z; As[lk + 7][lr] = a1.w;
        Ws[lk + 0][lr] = w0.x; Ws[lk + 1][lr] = w0.y; Ws[lk + 2][lr] = w0.z; Ws[lk + 3][lr] = w0.w;
        Ws[lk + 4][lr] = w1.x; Ws[lk + 5][lr] = w1.y; Ws[lk + 6][lr] = w1.z; Ws[lk + 7][lr] = w1.w;
        __syncthreads();
        if (kk0 + 16 < kchunk) {
            a0 = *(const float4*)(Ap + kk0 + 16);
            a1 = *(const float4*)(Ap + kk0 + 20);
            w0 = *(const float4*)(Wp + kk0 + 16);
            w1 = *(const float4*)(Wp + kk0 + 20);
        }
#pragma unroll
        for (int kk = 0; kk < 16; kk++) {
            float4 ra0 = *(const float4*)&As[kk][ty * 8];
            float4 ra1 = *(const float4*)&As[kk][ty * 8 + 4];
            float4 rw  = *(const float4*)&Ws[kk][tx * 4];
            acc[0][0] += ra0.x * rw.x; acc[0][1] += ra0.x * rw.y; acc[0][2] += ra0.x * rw.z; acc[0][3] += ra0.x * rw.w;
            acc[1][0] += ra0.y * rw.x; acc[1][1] += ra0.y * rw.y; acc[1][2] += ra0.y * rw.z; acc[1][3] += ra0.y * rw.w;
            acc[2][0] += ra0.z * rw.x; acc[2][1] += ra0.z * rw.y; acc[2][2] += ra0.z * rw.z; acc[2][3] += ra0.z * rw.w;
            acc[3][0] += ra0.w * rw.x; acc[3][1] += ra0.w * rw.y; acc[3][2] += ra0.w * rw.z; acc[3][3] += ra0.w * rw.w;
            acc[4][0] += ra1.x * rw.x; acc[4][1] += ra1.x * rw.y; acc[4][2] += ra1.x * rw.z; acc[4][3] += ra1.x * rw.w;
            acc[5][0] += ra1.y * rw.x; acc[5][1] += ra1.y * rw.y; acc[5][2] += ra1.y * rw.z; acc[5][3] += ra1.y * rw.w;
            acc[6][0] += ra1.z * rw.x; acc[6][1] += ra1.z * rw.y; acc[6][2] += ra1.z * rw.z; acc[6][3] += ra1.z * rw.w;
            acc[7][0] += ra1.w * rw.x; acc[7][1] += ra1.w * rw.y; acc[7][2] += ra1.w * rw.z; acc[7][3] += ra1.w * rw.w;
        }
    }
#pragma unroll
    for (int i = 0; i < 8; i++)
        *(float4*)(Cb + (size_t)(ty * 8 + i) * (2 * H) + n0 + tx * 4) =
            make_float4(acc[i][0], acc[i][1], acc[i][2], acc[i][3]);
}

// =====================================================================
// gemm_big: 128x128 tile, single-buffered (R15 measured-best) — att_enc.
// =====================================================================
__global__ void __launch_bounds__(256) gemm_big_k(
    const float* __restrict__ Am,
    const float* __restrict__ Wm,
    const float* __restrict__ bias,
    float* __restrict__ C)
{
    __shared__ float As[16][128];
    __shared__ float Ws[16][128];
    const int tid = threadIdx.x;
    const int n0 = blockIdx.x * 128;
    const int m0 = blockIdx.y * 128;
    const int lr = tid & 127;
    const int lk = (tid >> 7) * 8;
    const float* Ap = Am + (size_t)(m0 + lr) * ENC + lk;
    const float* Wp = Wm + (size_t)(n0 + lr) * ENC + lk;
    const int tx = tid & 15;
    const int ty = tid >> 4;

    float acc[8][8];
#pragma unroll
    for (int i = 0; i < 8; i++)
#pragma unroll
        for (int j = 0; j < 8; j++) acc[i][j] = 0.f;

    float4 a0 = *(const float4*)(Ap);
    float4 a1 = *(const float4*)(Ap + 4);
    float4 w0 = *(const float4*)(Wp);
    float4 w1 = *(const float4*)(Wp + 4);

    for (int k0 = 0; k0 < ENC; k0 += 16) {
        __syncthreads();
        As[lk + 0][lr] = a0.x; As[lk + 1][lr] = a0.y; As[lk + 2][lr] = a0.z; As[lk + 3][lr] = a0.w;
        As[lk + 4][lr] = a1.x; As[lk + 5][lr] = a1.y; As[lk + 6][lr] = a1.z; As[lk + 7][lr] = a1.w;
        Ws[lk + 0][lr] = w0.x; Ws[lk + 1][lr] = w0.y; Ws[lk + 2][lr] = w0.z; Ws[lk + 3][lr] = w0.w;
        Ws[lk + 4][lr] = w1.x; Ws[lk + 5][lr] = w1.y; Ws[lk + 6][lr] = w1.z; Ws[lk + 7][lr] = w1.w;
        __syncthreads();
        if (k0 + 16 < ENC) {
            a0 = *(const float4*)(Ap + k0 + 16);
            a1 = *(const float4*)(Ap + k0 + 20);
            w0 = *(const float4*)(Wp + k0 + 16);
            w1 = *(const float4*)(Wp + k0 + 20);
        }
#pragma unroll
        for (int kk = 0; kk < 16; kk++) {
            float4 ra0 = *(const float4*)&As[kk][ty * 8];
            float4 ra1 = *(const float4*)&As[kk][ty * 8 + 4];
            float4 rw0 = *(const float4*)&Ws[kk][tx * 4];
            float4 rw1 = *(const float4*)&Ws[kk][64 + tx * 4];
            const float aval[8] = {ra0.x, ra0.y, ra0.z, ra0.w, ra1.x, ra1.y, ra1.z, ra1.w};
            const float wval[8] = {rw0.x, rw0.y, rw0.z, rw0.w, rw1.x, rw1.y, rw1.z, rw1.w};
#pragma unroll
            for (int i = 0; i < 8; i++)
#pragma unroll
                for (int j = 0; j < 8; j++) acc[i][j] += aval[i] * wval[j];
        }
    }
#pragma unroll
    for (int i = 0; i < 8; i++) {
        const int m = m0 + ty * 8 + i;
#pragma unroll
        for (int jj = 0; jj < 2; jj++) {
            const int n = n0 + jj * 64 + tx * 4;
            const float4 bv = *(const float4*)(bias + n);
            float4 v = make_float4(acc[i][jj*4+0] + bv.x, acc[i][jj*4+1] + bv.y,
                                   acc[i][jj*4+2] + bv.z, acc[i][jj*4+3] + bv.w);
            *(float4*)(C + (size_t)m * A_DIM + n) = v;
        }
    }
}

// =====================================================================
// pred_big: batched vocab projection — conflict-free + double-buffered.
// =====================================================================
__global__ void __launch_bounds__(256) pred_big_k(
    const float* __restrict__ Wfc,
    const float* __restrict__ bfc,
    float* __restrict__ out)
{
    __shared__ float As[2][16][128];
    __shared__ float Ws[2][16][128];
    const int tid = threadIdx.x;
    const int n0 = blockIdx.x * 128;
    const int m0 = blockIdx.y * 128;
    const int lr = tid & 127;
    const int lk = (tid >> 7) * 8;
    const float* Ap = g_hsave + (size_t)(m0 + lr) * H + lk;
    const int wr = min(n0 + lr, V - 1);
    const float* Wp = Wfc + (size_t)wr * H + lk;
    const int tx = tid & 15;
    const int ty = tid >> 4;

    float acc[8][8];
#pragma unroll
    for (int i = 0; i < 8; i++)
#pragma unroll
        for (int j = 0; j < 8; j++) acc[i][j] = 0.f;

    float4 a0 = *(const float4*)(Ap);
    float4 a1 = *(const float4*)(Ap + 4);
    float4 w0 = *(const float4*)(Wp);
    float4 w1 = *(const float4*)(Wp + 4);
    As[0][lk + 0][lr] = a0.x; As[0][lk + 1][lr] = a0.y; As[0][lk + 2][lr] = a0.z; As[0][lk + 3][lr] = a0.w;
    As[0][lk + 4][lr] = a1.x; As[0][lk + 5][lr] = a1.y; As[0][lk + 6][lr] = a1.z; As[0][lk + 7][lr] = a1.w;
    Ws[0][lk + 0][lr] = w0.x; Ws[0][lk + 1][lr] = w0.y; Ws[0][lk + 2][lr] = w0.z; Ws[0][lk + 3][lr] = w0.w;
    Ws[0][lk + 4][lr] = w1.x; Ws[0][lk + 5][lr] = w1.y; Ws[0][lk + 6][lr] = w1.z; Ws[0][lk + 7][lr] = w1.w;
    __syncthreads();

    constexpr int NCH = H / 16;
    for (int c = 0; c < NCH; c++) {
        const int sb = c & 1;
        const bool more = (c + 1 < NCH);
        if (more) {
            a0 = *(const float4*)(Ap + (c + 1) * 16);
            a1 = *(const float4*)(Ap + (c + 1) * 16 + 4);
            w0 = *(const float4*)(Wp + (c + 1) * 16);
            w1 = *(const float4*)(Wp + (c + 1) * 16 + 4);
        }
#pragma unroll
        for (int kk = 0; kk < 16; kk++) {
            float4 ra0 = *(const float4*)&As[sb][kk][ty * 8];
            float4 ra1 = *(const float4*)&As[sb][kk][ty * 8 + 4];
            float4 rw0 = *(const float4*)&Ws[sb][kk][tx * 4];
            float4 rw1 = *(const float4*)&Ws[sb][kk][64 + tx * 4];
            const float aval[8] = {ra0.x, ra0.y, ra0.z, ra0.w, ra1.x, ra1.y, ra1.z, ra1.w};
            const float wval[8] = {rw0.x, rw0.y, rw0.z, rw0.w, rw1.x, rw1.y, rw1.z, rw1.w};
#pragma unroll
            for (int i = 0; i < 8; i++)
#pragma unroll
                for (int j = 0; j < 8; j++) acc[i][j] += aval[i] * wval[j];
        }
        if (more) {
            const int sn = sb ^ 1;
            As[sn][lk + 0][lr] = a0.x; As[sn][lk + 1][lr] = a0.y; As[sn][lk + 2][lr] = a0.z; As[sn][lk + 3][lr] = a0.w;
            As[sn][lk + 4][lr] = a1.x; As[sn][lk + 5][lr] = a1.y; As[sn][lk + 6][lr] = a1.z; As[sn][lk + 7][lr] = a1.w;
            Ws[sn][lk + 0][lr] = w0.x; Ws[sn][lk + 1][lr] = w0.y; Ws[sn][lk + 2][lr] = w0.z; Ws[sn][lk + 3][lr] = w0.w;
            Ws[sn][lk + 4][lr] = w1.x; Ws[sn][lk + 5][lr] = w1.y; Ws[sn][lk + 6][lr] = w1.z; Ws[sn][lk + 7][lr] = w1.w;
            __syncthreads();
        }
    }

#pragma unroll
    for (int i = 0; i < 8; i++) {
        const int r = m0 + ty * 8 + i;              // = t*64 + b
        if (r < (T - 1) * B) {
            const int t = r >> 6;
            const int b = r & 63;
            float* orow = out + (size_t)b * T * V + (size_t)t * V;
#pragma unroll
            for (int jj = 0; jj < 2; jj++) {
                const int n = n0 + jj * 64 + tx * 4;
                if (n < V) {
                    const float4 bv = *(const float4*)(bfc + n);
                    float4 v = make_float4(acc[i][jj*4+0] + bv.x, acc[i][jj*4+1] + bv.y,
                                           acc[i][jj*4+2] + bv.z, acc[i][jj*4+3] + bv.w);
                    *(float4*)(orow + n) = v;
                }
            }
        }
    }
}

// ---------------- mean over P (float4 vectorized) ----------------
__global__ void mean_k(const float* __restrict__ enc)
{
    const int idx = blockIdx.x * 256 + threadIdx.x;
    const int b = idx / (ENC / 4);
    const int e4 = idx - b * (ENC / 4);
    const float4* p = (const float4*)(enc + (size_t)b * P * ENC) + e4;
    float4 s = make_float4(0.f, 0.f, 0.f, 0.f);
    for (int pp = 0; pp < P; pp++) {
        const float4 v = p[(size_t)pp * (ENC / 4)];
        s.x += v.x; s.y += v.y; s.z += v.z; s.w += v.w;
    }
    const float r = 1.f / (float)P;
    s.x *= r; s.y *= r; s.z *= r; s.w *= r;
    ((float4*)g_mean)[idx] = s;
}

// ---------------- reduce dual h0/c0 partials ----------------
__global__ void reduce_hc_k(const float* __restrict__ bch, const float* __restrict__ bcc)
{
    const int idx = blockIdx.x * 256 + threadIdx.x;
    const int b = idx / (2 * H);
    const int n = idx - b * (2 * H);
    float s = (n < H) ? bch[n] : bcc[n - H];
    for (int ss = 0; ss < NS_HC; ss++) s += g_part[(size_t)(ss * 64 + b) * (2 * H) + n];
    if (n < H) g_h[b * H + n] = s;
    else       g_c[b * H + (n - H)] = s;
}

// ---------------- zero the final time step ----------------
__global__ void zero_k(float* __restrict__ out)
{
    const int idx = blockIdx.x * 256 + threadIdx.x;
    if (idx < B * V) {
        const int b = idx / V;
        const int n = idx - b * V;
        out[(size_t)b * T * V + (size_t)(T - 1) * V + n] = 0.f;
    }
}

// ---------------- launch ----------------
extern "C" void kernel_launch(void* const* d_in, const int* in_sizes, int n_in,
                              void* d_out, int out_size)
{
    const float* enc  = (const float*)d_in[0];
    const int*   cap  = (const int*)d_in[1];
    const float* emb  = (const float*)d_in[2];
    const float* W_ih = (const float*)d_in[3];
    const float* b_ih = (const float*)d_in[4];
    const float* W_hh = (const float*)d_in[5];
    const float* b_hh = (const float*)d_in[6];
    const float* We   = (const float*)d_in[7];
    const float* be   = (const float*)d_in[8];
    const float* Wh   = (const float*)d_in[9];
    const float* bh   = (const float*)d_in[10];
    const float* Wa   = (const float*)d_in[11];
    const float* ba   = (const float*)d_in[12];
    const float* Wch  = (const float*)d_in[13];
    const float* bch  = (const float*)d_in[14];
    const float* Wcc  = (const float*)d_in[15];
    const float* bcc  = (const float*)d_in[16];
    const float* Wfc  = (const float*)d_in[17];
    const float* bfc  = (const float*)d_in[18];
    const float* Wg   = (const float*)d_in[19];
    const float* bg   = (const float*)d_in[20];
    float* out = (float*)d_out;

    float *p_att_enc, *p_part, *p_mean;
    cudaGetSymbolAddress((void**)&p_att_enc, g_att_enc);
    cudaGetSymbolAddress((void**)&p_part,    g_part);
    cudaGetSymbolAddress((void**)&p_mean,    g_mean);

    // ---- setup ----
    mean_k<<<(B * ENC / 4) / 256, 256>>>(enc);
    gemm64_hc_k<<<dim3(2 * H / 64, NS_HC), 128>>>(p_mean, Wch, Wcc, p_part, ENC / NS_HC);
    reduce_hc_k<<<(B * 2 * H) / 256, 256>>>(bch, bcc);
    gemm_big_k<<<dim3(A_DIM / 128, (B * P) / 128), 256>>>(enc, We, be, p_att_enc);

    // ---- persistent recurrent loop (all 19 steps, 1 launch) ----
    loop_k<<<GRID, 256>>>(enc, cap, emb, W_ih, b_ih, W_hh, b_hh,
                          Wh, bh, Wa, ba, Wg, bg);

    // ---- batched vocab projection for all 19 steps ----
    pred_big_k<<<dim3((V + 127) / 128, MSAVE / 128), 256>>>(Wfc, bfc, out);

    // out[:, T-1, :] = 0
    zero_k<<<(B * V + 255) / 256, 256>>>(out);
}